// round 3
// baseline (speedup 1.0000x reference)
#include <cuda_runtime.h>
#include <math.h>

#define NN 100000
#define NE 6400000
#define F1 5     // F_IN
#define F2 5     // F_HID
#define F3 10    // F_OUT

// Scratch (no allocations allowed)
__device__ float g_deg[NN];
__device__ float g_agg[NN * F1];   // reused both layers (F1 == F2)
__device__ float g_h[NN * F2];

__device__ __forceinline__ float sigmoidf_(float z) {
    return 1.0f / (1.0f + __expf(-z));
}

// Zero agg + deg
__global__ void k_zero_all() {
    int i = blockIdx.x * blockDim.x + threadIdx.x;
    if (i < NN * F1) g_agg[i] = 0.0f;
    if (i < NN)      g_deg[i] = 0.0f;
}

// Zero agg only (deg reused for layer 2)
__global__ void k_zero_agg() {
    int i = blockIdx.x * blockDim.x + threadIdx.x;
    if (i < NN * F1) g_agg[i] = 0.0f;
}

// Edge pass 1: agg[dst] += x[src], deg[dst] += 1. 4 edges per thread via int4.
__global__ void k_edge1(const float* __restrict__ x,
                        const int4* __restrict__ src4,
                        const int4* __restrict__ dst4) {
    int t = blockIdx.x * blockDim.x + threadIdx.x;
    if (t >= NE / 4) return;
    int4 s4 = src4[t];
    int4 d4 = dst4[t];
    int ss[4] = {s4.x, s4.y, s4.z, s4.w};
    int dd[4] = {d4.x, d4.y, d4.z, d4.w};
#pragma unroll
    for (int k = 0; k < 4; k++) {
        const float* xs = x + ss[k] * F1;
        float v0 = __ldg(xs + 0);
        float v1 = __ldg(xs + 1);
        float v2 = __ldg(xs + 2);
        float v3 = __ldg(xs + 3);
        float v4 = __ldg(xs + 4);
        float* a = g_agg + dd[k] * F1;
        atomicAdd(a + 0, v0);
        atomicAdd(a + 1, v1);
        atomicAdd(a + 2, v2);
        atomicAdd(a + 3, v3);
        atomicAdd(a + 4, v4);
        atomicAdd(g_deg + dd[k], 1.0f);
    }
}

// Edge pass 2: agg[dst] += h[src]
__global__ void k_edge2(const int4* __restrict__ src4,
                        const int4* __restrict__ dst4) {
    int t = blockIdx.x * blockDim.x + threadIdx.x;
    if (t >= NE / 4) return;
    int4 s4 = src4[t];
    int4 d4 = dst4[t];
    int ss[4] = {s4.x, s4.y, s4.z, s4.w};
    int dd[4] = {d4.x, d4.y, d4.z, d4.w};
#pragma unroll
    for (int k = 0; k < 4; k++) {
        const float* hs = g_h + ss[k] * F2;
        float v0 = hs[0];
        float v1 = hs[1];
        float v2 = hs[2];
        float v3 = hs[3];
        float v4 = hs[4];
        float* a = g_agg + dd[k] * F1;
        atomicAdd(a + 0, v0);
        atomicAdd(a + 1, v1);
        atomicAdd(a + 2, v2);
        atomicAdd(a + 3, v3);
        atomicAdd(a + 4, v4);
    }
}

// Node pass 1: h = sigmoid(x @ Ws1 + (agg/deg) @ Wn1 + b1)
__global__ void k_node1(const float* __restrict__ x,
                        const float* __restrict__ Ws,
                        const float* __restrict__ Wn,
                        const float* __restrict__ b) {
    int v = blockIdx.x * blockDim.x + threadIdx.x;
    if (v >= NN) return;
    float inv = 1.0f / fmaxf(g_deg[v], 1.0f);
    float xs[F1], xn[F1];
#pragma unroll
    for (int i = 0; i < F1; i++) {
        xs[i] = x[v * F1 + i];
        xn[i] = g_agg[v * F1 + i] * inv;
    }
#pragma unroll
    for (int j = 0; j < F2; j++) {
        float z = __ldg(b + j);
#pragma unroll
        for (int i = 0; i < F1; i++) {
            z = fmaf(xs[i], __ldg(Ws + i * F2 + j), z);
            z = fmaf(xn[i], __ldg(Wn + i * F2 + j), z);
        }
        g_h[v * F2 + j] = sigmoidf_(z);
    }
}

// Node pass 2: out = sigmoid(h @ Ws2 + (agg/deg) @ Wn2 + b2)
__global__ void k_node2(float* __restrict__ out,
                        const float* __restrict__ Ws,
                        const float* __restrict__ Wn,
                        const float* __restrict__ b) {
    int v = blockIdx.x * blockDim.x + threadIdx.x;
    if (v >= NN) return;
    float inv = 1.0f / fmaxf(g_deg[v], 1.0f);
    float hs[F2], hn[F2];
#pragma unroll
    for (int i = 0; i < F2; i++) {
        hs[i] = g_h[v * F2 + i];
        hn[i] = g_agg[v * F2 + i] * inv;
    }
#pragma unroll
    for (int j = 0; j < F3; j++) {
        float z = __ldg(b + j);
#pragma unroll
        for (int i = 0; i < F2; i++) {
            z = fmaf(hs[i], __ldg(Ws + i * F3 + j), z);
            z = fmaf(hn[i], __ldg(Wn + i * F3 + j), z);
        }
        out[v * F3 + j] = sigmoidf_(z);
    }
}

extern "C" void kernel_launch(void* const* d_in, const int* in_sizes, int n_in,
                              void* d_out, int out_size) {
    const float* x   = (const float*)d_in[0];
    const int*   src = (const int*)d_in[1];
    const int*   dst = (const int*)d_in[2];
    const float* Ws1 = (const float*)d_in[3];
    const float* Wn1 = (const float*)d_in[4];
    const float* b1  = (const float*)d_in[5];
    const float* Ws2 = (const float*)d_in[6];
    const float* Wn2 = (const float*)d_in[7];
    const float* b2  = (const float*)d_in[8];
    float* out = (float*)d_out;

    const int ZB = 256;
    int zgrid = (NN * F1 + ZB - 1) / ZB;

    const int EB = 256;
    int egrid = (NE / 4 + EB - 1) / EB;

    const int VB = 256;
    int vgrid = (NN + VB - 1) / VB;

    k_zero_all<<<zgrid, ZB>>>();
    k_edge1<<<egrid, EB>>>(x, (const int4*)src, (const int4*)dst);
    k_node1<<<vgrid, VB>>>(x, Ws1, Wn1, b1);
    k_zero_agg<<<zgrid, ZB>>>();
    k_edge2<<<egrid, EB>>>((const int4*)src, (const int4*)dst);
    k_node2<<<vgrid, VB>>>(out, Ws2, Wn2, b2);
}

// round 4
// speedup vs baseline: 2.1877x; 2.1877x over previous
#include <cuda_runtime.h>
#include <math.h>

#define NN 100000
#define NE 6400000
#define F1 5     // F_IN
#define F2 5     // F_HID
#define F3 10    // F_OUT
#define PAD 8    // padded row width

// Scratch (no allocations allowed)
// g_acc row layout: [f0 f1 f2 f3 f4 deg unused unused]
__device__ float g_acc[NN * PAD];
// g_node row layout: [f0 f1 f2 f3 f4 x x x]  (x in pass1, h in pass2)
__device__ float g_node[NN * PAD];

__device__ __forceinline__ float sigmoidf_(float z) {
    return 1.0f / (1.0f + __expf(-z));
}

__device__ __forceinline__ void red_v4(float* p, float a, float b, float c, float d) {
    asm volatile("red.global.add.v4.f32 [%0], {%1, %2, %3, %4};"
                 :: "l"(p), "f"(a), "f"(b), "f"(c), "f"(d) : "memory");
}
__device__ __forceinline__ void red_v2(float* p, float a, float b) {
    asm volatile("red.global.add.v2.f32 [%0], {%1, %2};"
                 :: "l"(p), "f"(a), "f"(b) : "memory");
}

// Prep: zero accumulator, copy x into padded node buffer
__global__ void k_prep(const float* __restrict__ x) {
    int v = blockIdx.x * blockDim.x + threadIdx.x;
    if (v >= NN) return;
    float4 z4 = make_float4(0.f, 0.f, 0.f, 0.f);
    *(float4*)(g_acc + v * PAD)     = z4;
    *(float4*)(g_acc + v * PAD + 4) = z4;
    const float* xs = x + v * F1;
    float f0 = xs[0], f1 = xs[1], f2 = xs[2], f3 = xs[3], f4 = xs[4];
    *(float4*)(g_node + v * PAD) = make_float4(f0, f1, f2, f3);
    g_node[v * PAD + 4] = f4;
}

// Edge pass: acc[dst] += node[src] (vectorized reds). degInc=1 for pass1, 0 for pass2.
template <int DEG>
__global__ void k_edge(const int4* __restrict__ src4,
                       const int4* __restrict__ dst4) {
    int t = blockIdx.x * blockDim.x + threadIdx.x;
    if (t >= NE / 4) return;
    int4 s4 = src4[t];
    int4 d4 = dst4[t];
    int ss[4] = {s4.x, s4.y, s4.z, s4.w};
    int dd[4] = {d4.x, d4.y, d4.z, d4.w};
    float4 v[4];
    float  e[4];
#pragma unroll
    for (int k = 0; k < 4; k++) {
        const float* ns = g_node + ss[k] * PAD;
        v[k] = *(const float4*)ns;
        e[k] = ns[4];
    }
#pragma unroll
    for (int k = 0; k < 4; k++) {
        float* a = g_acc + dd[k] * PAD;
        red_v4(a, v[k].x, v[k].y, v[k].z, v[k].w);
        red_v2(a + 4, e[k], (float)DEG);
    }
}

// Node pass 1: h = sigmoid(x @ Ws1 + (acc/deg) @ Wn1 + b1), write padded h,
// and re-zero acc feature slots (deg slot preserved for layer 2).
__global__ void k_node1(const float* __restrict__ Ws,
                        const float* __restrict__ Wn,
                        const float* __restrict__ b) {
    int v = blockIdx.x * blockDim.x + threadIdx.x;
    if (v >= NN) return;
    float* ac = g_acc + v * PAD;
    float4 a4 = *(float4*)ac;
    float  a5 = ac[4];
    float  deg = ac[5];
    float inv = 1.0f / fmaxf(deg, 1.0f);
    float* ns = g_node + v * PAD;
    float4 x4 = *(float4*)ns;
    float  x5 = ns[4];
    float xs[F1] = {x4.x, x4.y, x4.z, x4.w, x5};
    float xn[F1] = {a4.x * inv, a4.y * inv, a4.z * inv, a4.w * inv, a5 * inv};
    float h[F2];
#pragma unroll
    for (int j = 0; j < F2; j++) {
        float z = __ldg(b + j);
#pragma unroll
        for (int i = 0; i < F1; i++) {
            z = fmaf(xs[i], __ldg(Ws + i * F2 + j), z);
            z = fmaf(xn[i], __ldg(Wn + i * F2 + j), z);
        }
        h[j] = sigmoidf_(z);
    }
    // write padded h
    *(float4*)ns = make_float4(h[0], h[1], h[2], h[3]);
    ns[4] = h[4];
    // re-zero acc feature slots, keep deg (slot 5)
    *(float4*)ac = make_float4(0.f, 0.f, 0.f, 0.f);
    ac[4] = 0.f;
}

// Node pass 2: out = sigmoid(h @ Ws2 + (acc/deg) @ Wn2 + b2)
__global__ void k_node2(float* __restrict__ out,
                        const float* __restrict__ Ws,
                        const float* __restrict__ Wn,
                        const float* __restrict__ b) {
    int v = blockIdx.x * blockDim.x + threadIdx.x;
    if (v >= NN) return;
    const float* ac = g_acc + v * PAD;
    float4 a4 = *(const float4*)ac;
    float  a5 = ac[4];
    float  deg = ac[5];
    float inv = 1.0f / fmaxf(deg, 1.0f);
    const float* ns = g_node + v * PAD;
    float4 h4 = *(const float4*)ns;
    float  h5 = ns[4];
    float hs[F2] = {h4.x, h4.y, h4.z, h4.w, h5};
    float hn[F2] = {a4.x * inv, a4.y * inv, a4.z * inv, a4.w * inv, a5 * inv};
#pragma unroll
    for (int j = 0; j < F3; j++) {
        float z = __ldg(b + j);
#pragma unroll
        for (int i = 0; i < F2; i++) {
            z = fmaf(hs[i], __ldg(Ws + i * F3 + j), z);
            z = fmaf(hn[i], __ldg(Wn + i * F3 + j), z);
        }
        out[v * F3 + j] = sigmoidf_(z);
    }
}

extern "C" void kernel_launch(void* const* d_in, const int* in_sizes, int n_in,
                              void* d_out, int out_size) {
    const float* x   = (const float*)d_in[0];
    const int*   src = (const int*)d_in[1];
    const int*   dst = (const int*)d_in[2];
    const float* Ws1 = (const float*)d_in[3];
    const float* Wn1 = (const float*)d_in[4];
    const float* b1  = (const float*)d_in[5];
    const float* Ws2 = (const float*)d_in[6];
    const float* Wn2 = (const float*)d_in[7];
    const float* b2  = (const float*)d_in[8];
    float* out = (float*)d_out;

    const int VB = 256;
    int vgrid = (NN + VB - 1) / VB;

    const int EB = 256;
    int egrid = (NE / 4 + EB - 1) / EB;

    k_prep<<<vgrid, VB>>>(x);
    k_edge<1><<<egrid, EB>>>((const int4*)src, (const int4*)dst);
    k_node1<<<vgrid, VB>>>(Ws1, Wn1, b1);
    k_edge<0><<<egrid, EB>>>((const int4*)src, (const int4*)dst);
    k_node2<<<vgrid, VB>>>(out, Ws2, Wn2, b2);
}

// round 6
// speedup vs baseline: 3.3567x; 1.5343x over previous
#include <cuda_runtime.h>
#include <cuda_fp16.h>
#include <math.h>

#define NN 100000
#define NE 6400000
#define F1 5     // F_IN
#define F2 5     // F_HID
#define F3 10    // F_OUT

// Scratch (no allocations allowed)
// Packed fp16 gather table: 8 halfs/node = 16B: [f0 f1 f2 f3 f4 degslot pad pad]
__device__ uint4 g_gath16[NN];
// Packed fp16 accumulator: same lane layout, accumulated via red.v4.f16x2
__device__ uint4 g_acc16[NN];
// Full-precision h for the layer-2 self term
__device__ float g_h32[NN * F2];
// Degree saved after pass 1 (acc row gets re-zeroed for pass 2)
__device__ float g_deg32[NN];

__device__ __forceinline__ float sigmoidf_(float z) {
    return 1.0f / (1.0f + __expf(-z));
}

__device__ __forceinline__ unsigned packh2(float a, float b) {
    unsigned lo = __half_as_ushort(__float2half_rn(a));
    unsigned hi = __half_as_ushort(__float2half_rn(b));
    return lo | (hi << 16);
}
__device__ __forceinline__ float loh(unsigned w) {
    return __half2float(__ushort_as_half((unsigned short)(w & 0xFFFF)));
}
__device__ __forceinline__ float hih(unsigned w) {
    return __half2float(__ushort_as_half((unsigned short)(w >> 16)));
}

// Single 16B half-precision vector reduction: 8 half lanes in one LTS op.
__device__ __forceinline__ void red_v4h2(uint4* p, unsigned a, unsigned b,
                                         unsigned c, unsigned d) {
    asm volatile("red.global.add.noftz.v4.f16x2 [%0], {%1, %2, %3, %4};"
                 :: "l"(p), "r"(a), "r"(b), "r"(c), "r"(d) : "memory");
}

// Prep: zero accumulator, quantize x into packed gather table
__global__ void k_prep(const float* __restrict__ x) {
    int v = blockIdx.x * blockDim.x + threadIdx.x;
    if (v >= NN) return;
    const float* xs = x + v * F1;
    unsigned w0 = packh2(xs[0], xs[1]);
    unsigned w1 = packh2(xs[2], xs[3]);
    unsigned w2 = packh2(xs[4], 0.0f);   // deg slot starts at 0
    g_gath16[v] = make_uint4(w0, w1, w2, 0u);
    g_acc16[v]  = make_uint4(0u, 0u, 0u, 0u);
}

// Edge pass: acc16[dst] += gath16[src], one LDG.128 + one red.v4.f16x2 per edge.
// DEG=1: also add 1.0h into the deg lane (high half of word 2).
template <int DEG>
__global__ void k_edge(const int4* __restrict__ src4,
                       const int4* __restrict__ dst4) {
    int t = blockIdx.x * blockDim.x + threadIdx.x;
    if (t >= NE / 4) return;
    int4 s4 = src4[t];
    int4 d4 = dst4[t];
    int ss[4] = {s4.x, s4.y, s4.z, s4.w};
    int dd[4] = {d4.x, d4.y, d4.z, d4.w};
    uint4 g[4];
#pragma unroll
    for (int k = 0; k < 4; k++) g[k] = g_gath16[ss[k]];
#pragma unroll
    for (int k = 0; k < 4; k++) {
        unsigned w2 = g[k].z;
        if (DEG) w2 |= 0x3C000000u;   // +1.0h in deg lane (stored deg-half is 0)
        red_v4h2(&g_acc16[dd[k]], g[k].x, g[k].y, w2, g[k].w);
    }
}

// Node pass 1: h = sigmoid(x @ Ws1 + (acc/deg) @ Wn1 + b1)
// Writes: fp32 h (self term of layer 2), packed CENTERED h-0.5 (gather table),
// saved deg, and re-zeroed accumulator.
__global__ void k_node1(const float* __restrict__ x,
                        const float* __restrict__ Ws,
                        const float* __restrict__ Wn,
                        const float* __restrict__ b) {
    int v = blockIdx.x * blockDim.x + threadIdx.x;
    if (v >= NN) return;
    uint4 a = g_acc16[v];
    float deg = hih(a.z);
    float inv = 1.0f / fmaxf(deg, 1.0f);
    float xn[F1] = { loh(a.x) * inv, hih(a.x) * inv,
                     loh(a.y) * inv, hih(a.y) * inv,
                     loh(a.z) * inv };
    float xs[F1];
#pragma unroll
    for (int i = 0; i < F1; i++) xs[i] = x[v * F1 + i];
    float h[F2];
#pragma unroll
    for (int j = 0; j < F2; j++) {
        float z = __ldg(b + j);
#pragma unroll
        for (int i = 0; i < F1; i++) {
            z = fmaf(xs[i], __ldg(Ws + i * F2 + j), z);
            z = fmaf(xn[i], __ldg(Wn + i * F2 + j), z);
        }
        h[j] = sigmoidf_(z);
    }
#pragma unroll
    for (int j = 0; j < F2; j++) g_h32[v * F2 + j] = h[j];
    // Centered h-0.5 keeps fp16 sums small (|sum| ~ sqrt(deg)/4, not deg/2)
    unsigned w0 = packh2(h[0] - 0.5f, h[1] - 0.5f);
    unsigned w1 = packh2(h[2] - 0.5f, h[3] - 0.5f);
    unsigned w2 = packh2(h[4] - 0.5f, 0.0f);
    g_gath16[v] = make_uint4(w0, w1, w2, 0u);
    g_deg32[v]  = deg;
    g_acc16[v]  = make_uint4(0u, 0u, 0u, 0u);
}

// Node pass 2: out = sigmoid(h @ Ws2 + (acc_c/deg + 0.5) @ Wn2 + b2)
__global__ void k_node2(float* __restrict__ out,
                        const float* __restrict__ Ws,
                        const float* __restrict__ Wn,
                        const float* __restrict__ b) {
    int v = blockIdx.x * blockDim.x + threadIdx.x;
    if (v >= NN) return;
    uint4 a = g_acc16[v];
    float deg = g_deg32[v];
    float inv = 1.0f / fmaxf(deg, 1.0f);
    // De-center: mean(h) = mean(h-0.5) + 0.5  (only where deg>0; deg==0 must give 0)
    float half_off = (deg > 0.0f) ? 0.5f : 0.0f;
    float hn[F2] = { loh(a.x) * inv + half_off, hih(a.x) * inv + half_off,
                     loh(a.y) * inv + half_off, hih(a.y) * inv + half_off,
                     loh(a.z) * inv + half_off };
    float hs[F2];
#pragma unroll
    for (int i = 0; i < F2; i++) hs[i] = g_h32[v * F2 + i];
#pragma unroll
    for (int j = 0; j < F3; j++) {
        float z = __ldg(b + j);
#pragma unroll
        for (int i = 0; i < F2; i++) {
            z = fmaf(hs[i], __ldg(Ws + i * F3 + j), z);
            z = fmaf(hn[i], __ldg(Wn + i * F3 + j), z);
        }
        out[v * F3 + j] = sigmoidf_(z);
    }
}

extern "C" void kernel_launch(void* const* d_in, const int* in_sizes, int n_in,
                              void* d_out, int out_size) {
    const float* x   = (const float*)d_in[0];
    const int*   src = (const int*)d_in[1];
    const int*   dst = (const int*)d_in[2];
    const float* Ws1 = (const float*)d_in[3];
    const float* Wn1 = (const float*)d_in[4];
    const float* b1  = (const float*)d_in[5];
    const float* Ws2 = (const float*)d_in[6];
    const float* Wn2 = (const float*)d_in[7];
    const float* b2  = (const float*)d_in[8];
    float* out = (float*)d_out;

    const int VB = 256;
    int vgrid = (NN + VB - 1) / VB;

    const int EB = 256;
    int egrid = (NE / 4 + EB - 1) / EB;

    k_prep<<<vgrid, VB>>>(x);
    k_edge<1><<<egrid, EB>>>((const int4*)src, (const int4*)dst);
    k_node1<<<vgrid, VB>>>(x, Ws1, Wn1, b1);
    k_edge<0><<<egrid, EB>>>((const int4*)src, (const int4*)dst);
    k_node2<<<vgrid, VB>>>(out, Ws2, Wn2, b2);
}